// round 7
// baseline (speedup 1.0000x reference)
#include <cuda_runtime.h>
#include <cstdint>

// Problem constants
#define PB   64
#define PS   1024
#define PF   768
#define PH   12
#define PP2  64
#define HEADSZ 4096
#define QKVSTRIDE (PB * PH * HEADSZ)   // 3,145,728

__device__ float g_qkv[3LL * QKVSTRIDE];
__device__ float g_o[4096LL * PF];

// ---------------------------------------------------------------------------
// PTX helpers
// ---------------------------------------------------------------------------
__device__ __forceinline__ void cp16(void* s, const void* g) {
    unsigned sa = (unsigned)__cvta_generic_to_shared(s);
    asm volatile("cp.async.cg.shared.global [%0], [%1], 16;\n" :: "r"(sa), "l"(g));
}
__device__ __forceinline__ void cp_commit() { asm volatile("cp.async.commit_group;\n"); }
template <int N>
__device__ __forceinline__ void cp_wait() { asm volatile("cp.async.wait_group %0;\n" :: "n"(N)); }

__device__ __forceinline__ void mma_tf32(float* c, const unsigned* a, const unsigned* b) {
    asm volatile(
        "mma.sync.aligned.m16n8k8.row.col.f32.tf32.tf32.f32 "
        "{%0,%1,%2,%3}, {%4,%5,%6,%7}, {%8,%9}, {%0,%1,%2,%3};"
        : "+f"(c[0]), "+f"(c[1]), "+f"(c[2]), "+f"(c[3])
        : "r"(a[0]), "r"(a[1]), "r"(a[2]), "r"(a[3]), "r"(b[0]), "r"(b[1]));
}

// ---------------------------------------------------------------------------
// TF32 mma.sync GEMM. Block tile 128x128, BK=32, 3-stage cp.async,
// ONE __syncthreads per K-iteration. 8 warps as 2(M) x 4(N), warp tile 64x32.
// MODE 0: C[4096,2304] = Xw @ [Wq;Wk;Wv]^T + bias -> g_qkv[which][b][h][s][d]
//         grid is 1D, 768 blocks: every 4th block is a tail-copy block.
// MODE 1: C[4096, 768] = O  @ Wo^T         + bo   -> d_out[b][s][c] (s < 64)
// ---------------------------------------------------------------------------
#define BK   32
#define LDK  36                         // 32 + 4: 16B-aligned rows, conflict-free frags
#define STAGEF ((128 + 128) * LDK)      // 9216 floats / stage
#define NSTG 3
#define DSMEM  (NSTG * STAGEF * 4)      // 110592 B -> 2 CTAs/SM
#define NKI  (PF / BK)                  // 24

#define NCOPY 192
#define CCHUNK 61440                    // float4 per copy block; 192*61440 = 64*960*192

template <int MODE>
__global__ void __launch_bounds__(256, 2) tc_gemm(
    const float* __restrict__ A,
    const float* __restrict__ W0, const float* __restrict__ W1, const float* __restrict__ W2,
    const float* __restrict__ b0, const float* __restrict__ b1, const float* __restrict__ b2,
    float* __restrict__ Cout)
{
    extern __shared__ float sm[];

    const int tid  = threadIdx.x;
    int bid = blockIdx.x;

    if (MODE == 0) {
        // Every 4th block streams a slice of x[:,64:,:] -> out[:,64:,:]
        if ((bid & 3) == 3) {
            int cb = bid >> 2;                       // 0..191
            const float4* src = (const float4*)A;
            float4* dst = (float4*)Cout;
            const int PERB = (PS - PP2) * (PF / 4);  // 184320
            int base = cb * CCHUNK;
            #pragma unroll 4
            for (int t = tid; t < CCHUNK; t += 256) {
                int i = base + t;
                int b = i / PERB;
                int rem = i - b * PERB;
                long long off = (long long)b * (PS * (PF / 4)) + PP2 * (PF / 4) + rem;
                __stcs(dst + off, __ldcs(src + off));
            }
            return;
        }
        bid -= (bid >> 2);               // compact to 0..575
    }

    const int wid  = tid >> 5;
    const int lane = tid & 31;
    const int wm   = wid >> 2;           // 0..1
    const int wn   = wid & 3;            // 0..3
    const int g    = lane >> 2;          // 0..7
    const int t4   = lane & 3;           // 0..3

    const int m0 = (bid & 31) * 128;
    const int ny = (MODE == 0) ? (bid >> 5) : (bid >> 5);   // n-tile index

    const float* W; const float* bias; int nbw; int wsel = 0;
    if (MODE == 0) {
        wsel = ny / 6;
        nbw  = (ny % 6) * 128;
        W    = (wsel == 0) ? W0 : (wsel == 1 ? W1 : W2);
        bias = (wsel == 0) ? b0 : (wsel == 1 ? b1 : b2);
    } else {
        W = W0; bias = b0; nbw = ny * 128;
    }
    const float* Ap = (MODE == 0) ? A : g_o;

    // Stage loader: A 128x32 + B 128x32, 4+4 cp16 per thread
    auto load_stage = [&](int buf, int k0) {
        float* As = sm + buf * STAGEF;
        float* Bs = As + 128 * LDK;
        #pragma unroll
        for (int p = 0; p < 4; p++) {
            int idx = tid + p * 256;
            int r = idx >> 3, c4 = (idx & 7) * 4;
            int gm = m0 + r;
            const float* ga = (MODE == 0)
                ? Ap + ((long long)(gm >> 6) * PS + (gm & 63)) * PF + k0 + c4
                : Ap + (long long)gm * PF + k0 + c4;
            cp16(&As[r * LDK + c4], ga);
        }
        #pragma unroll
        for (int p = 0; p < 4; p++) {
            int idx = tid + p * 256;
            int r = idx >> 3, c4 = (idx & 7) * 4;
            const float* gb = W + (long long)(nbw + r) * PF + k0 + c4;
            cp16(&Bs[r * LDK + c4], gb);
        }
    };

    float acc[4][4][4];
    #pragma unroll
    for (int mi = 0; mi < 4; mi++)
        #pragma unroll
        for (int ni = 0; ni < 4; ni++)
            #pragma unroll
            for (int q = 0; q < 4; q++) acc[mi][ni][q] = 0.0f;

    load_stage(0, 0);
    cp_commit();
    load_stage(1, BK);
    cp_commit();

    int buf = 0;
    for (int i = 0; i < NKI; i++) {
        if (i < NKI - 1) { cp_wait<1>(); } else { cp_wait<0>(); }
        __syncthreads();
        if (i + 2 < NKI) {
            int lb = buf + 2; if (lb >= NSTG) lb -= NSTG;
            load_stage(lb, (i + 2) * BK);
            cp_commit();
        }

        const float* As = sm + buf * STAGEF;
        const float* Bs = As + 128 * LDK;
        const float* ab = As + (wm * 64 + g) * LDK + t4;
        const float* bb = Bs + (wn * 32 + g) * LDK + t4;

        #pragma unroll
        for (int kk = 0; kk < BK; kk += 8) {
            unsigned af[4][4];
            #pragma unroll
            for (int mi = 0; mi < 4; mi++) {
                const float* p = ab + mi * 16 * LDK + kk;
                af[mi][0] = __float_as_uint(p[0]);
                af[mi][1] = __float_as_uint(p[8 * LDK]);
                af[mi][2] = __float_as_uint(p[4]);
                af[mi][3] = __float_as_uint(p[8 * LDK + 4]);
            }
            unsigned bf[4][2];
            #pragma unroll
            for (int ni = 0; ni < 4; ni++) {
                const float* p = bb + ni * 8 * LDK + kk;
                bf[ni][0] = __float_as_uint(p[0]);
                bf[ni][1] = __float_as_uint(p[4]);
            }
            #pragma unroll
            for (int mi = 0; mi < 4; mi++)
                #pragma unroll
                for (int ni = 0; ni < 4; ni++)
                    mma_tf32(acc[mi][ni], af[mi], bf[ni]);
        }

        buf++; if (buf >= NSTG) buf -= NSTG;
    }

    // Bias per ni (float2, col pair this thread owns)
    float2 bfrag[4];
    #pragma unroll
    for (int ni = 0; ni < 4; ni++)
        bfrag[ni] = *reinterpret_cast<const float2*>(bias + nbw + wn * 32 + ni * 8 + t4 * 2);

    // Epilogue: direct global float2 stores from accumulators
    #pragma unroll
    for (int mi = 0; mi < 4; mi++) {
        #pragma unroll
        for (int half = 0; half < 2; half++) {
            int gm = m0 + wm * 64 + mi * 16 + g + half * 8;
            int bb_ = gm >> 6, ss_ = gm & 63;
            #pragma unroll
            for (int ni = 0; ni < 4; ni++) {
                int n = nbw + wn * 32 + ni * 8 + t4 * 2;
                float2 v;
                v.x = acc[mi][ni][half * 2 + 0] + bfrag[ni].x;
                v.y = acc[mi][ni][half * 2 + 1] + bfrag[ni].y;
                if (MODE == 0) {
                    int h = n >> 6, d = n & 63;
                    float* dst = g_qkv + (long long)wsel * QKVSTRIDE
                               + (long long)(bb_ * PH + h) * HEADSZ + ss_ * 64 + d;
                    *reinterpret_cast<float2*>(dst) = v;
                } else {
                    float* dst = Cout + ((long long)bb_ * PS + ss_) * PF + n;
                    *reinterpret_cast<float2*>(dst) = v;
                }
            }
        }
    }
}

// ---------------------------------------------------------------------------
// Attention, one block per (b,h). 64x64 q,k,v tiles in smem.
// ---------------------------------------------------------------------------
__global__ void __launch_bounds__(256) attn_kernel() {
    __shared__ float sq[64 * 64];
    __shared__ float sk[64 * 64];
    __shared__ float ss[64 * 64];

    const int tid = threadIdx.x;
    const int b = blockIdx.x / PH;
    const int h = blockIdx.x % PH;
    const float* qg = g_qkv + (long long)(b * PH + h) * HEADSZ;
    const float* kg = qg + (long long)QKVSTRIDE;
    const float* vg = kg + (long long)QKVSTRIDE;
    const int lane = tid & 31;

    for (int t = tid; t < 1024; t += 256)
        reinterpret_cast<float4*>(sq)[t] = reinterpret_cast<const float4*>(qg)[t];
    for (int t = tid; t < 1024; t += 256) {
        int j = t >> 4, d4 = (t & 15) * 4;
        float4 v = reinterpret_cast<const float4*>(kg)[t];
        *reinterpret_cast<float4*>(&sk[j * 64 + (d4 ^ ((j & 7) << 3))]) = v;
    }
    __syncthreads();

    #pragma unroll
    for (int t = 0; t < 16; t++) {
        int idx = tid + (t << 8);
        int i = idx >> 6, j = idx & 63;
        int sw = (j & 7) << 3;
        float s = 0.f;
        #pragma unroll
        for (int dd = 0; dd < 64; dd += 4) {
            float4 q4 = *reinterpret_cast<const float4*>(&sq[i * 64 + dd]);
            float4 k4 = *reinterpret_cast<const float4*>(&sk[j * 64 + (dd ^ sw)]);
            s += q4.x * k4.x + q4.y * k4.y + q4.z * k4.z + q4.w * k4.w;
        }
        ss[idx] = s * 0.125f;
    }
    __syncthreads();

    {
        int w = tid >> 5;
        #pragma unroll
        for (int rr = 0; rr < 8; rr++) {
            int i = w * 8 + rr;
            float x0 = ss[i * 64 + lane];
            float x1 = ss[i * 64 + 32 + lane];
            float m = fmaxf(x0, x1);
            #pragma unroll
            for (int o = 16; o; o >>= 1) m = fmaxf(m, __shfl_xor_sync(0xffffffffu, m, o));
            float e0 = __expf(x0 - m), e1 = __expf(x1 - m);
            float sum = e0 + e1;
            #pragma unroll
            for (int o = 16; o; o >>= 1) sum += __shfl_xor_sync(0xffffffffu, sum, o);
            float inv = 1.0f / sum;
            ss[i * 64 + lane]      = e0 * inv;
            ss[i * 64 + 32 + lane] = e1 * inv;
        }
    }
    __syncthreads();

    for (int t = tid; t < 1024; t += 256)
        reinterpret_cast<float4*>(sq)[t] = reinterpret_cast<const float4*>(vg)[t];
    __syncthreads();

    #pragma unroll
    for (int t = 0; t < 4; t++) {
        int gidx = tid + (t << 8);
        int i  = gidx >> 4;
        int d4 = (gidx & 15) * 4;
        float ox = 0.f, oy = 0.f, oz = 0.f, ow = 0.f;
        #pragma unroll 16
        for (int j = 0; j < 64; j++) {
            float a = ss[i * 64 + j];
            float4 v4 = *reinterpret_cast<const float4*>(&sq[j * 64 + d4]);
            ox += a * v4.x; oy += a * v4.y; oz += a * v4.z; ow += a * v4.w;
        }
        float4 o4; o4.x = ox; o4.y = oy; o4.z = oz; o4.w = ow;
        *reinterpret_cast<float4*>(&g_o[(long long)(b * 64 + i) * PF + h * 64 + d4]) = o4;
    }
}

// ---------------------------------------------------------------------------
extern "C" void kernel_launch(void* const* d_in, const int* in_sizes, int n_in,
                              void* d_out, int out_size) {
    const float* x  = (const float*)d_in[0];
    const float* Wq = (const float*)d_in[1];
    const float* bq = (const float*)d_in[2];
    const float* Wk = (const float*)d_in[3];
    const float* bk = (const float*)d_in[4];
    const float* Wv = (const float*)d_in[5];
    const float* bv = (const float*)d_in[6];
    const float* Wo = (const float*)d_in[7];
    const float* bo = (const float*)d_in[8];
    float* out = (float*)d_out;

    cudaFuncSetAttribute(tc_gemm<0>, cudaFuncAttributeMaxDynamicSharedMemorySize, DSMEM);
    cudaFuncSetAttribute(tc_gemm<1>, cudaFuncAttributeMaxDynamicSharedMemorySize, DSMEM);

    // 1) QKV projection (+bias) into g_qkv, with interleaved tail-copy blocks
    //    576 gemm blocks + 192 copy blocks (every 4th)
    tc_gemm<0><<<768, 256, DSMEM>>>(x, Wq, Wk, Wv, bq, bk, bv, out);

    // 2) attention per (b,h)
    attn_kernel<<<PB * PH, 256>>>();

    // 3) output projection (+bo) into d_out[:, :64, :]: 192 blocks
    tc_gemm<1><<<192, 256, DSMEM>>>(nullptr, Wo, nullptr, nullptr,
                                    bo, nullptr, nullptr, out);
}

// round 8
// speedup vs baseline: 1.0006x; 1.0006x over previous
#include <cuda_runtime.h>
#include <cstdint>

// Problem constants
#define PB   64
#define PS   1024
#define PF   768
#define PH   12
#define PP2  64
#define HEADSZ 4096
#define QKVSTRIDE (PB * PH * HEADSZ)   // 3,145,728

__device__ float g_qkv[3LL * QKVSTRIDE];
__device__ float g_o[4096LL * PF];

// ---------------------------------------------------------------------------
// PTX helpers
// ---------------------------------------------------------------------------
__device__ __forceinline__ void cp16(void* s, const void* g) {
    unsigned sa = (unsigned)__cvta_generic_to_shared(s);
    asm volatile("cp.async.cg.shared.global [%0], [%1], 16;\n" :: "r"(sa), "l"(g));
}
__device__ __forceinline__ void cp_commit() { asm volatile("cp.async.commit_group;\n"); }
template <int N>
__device__ __forceinline__ void cp_wait() { asm volatile("cp.async.wait_group %0;\n" :: "n"(N)); }

__device__ __forceinline__ void mma_tf32(float* c, const unsigned* a, const unsigned* b) {
    asm volatile(
        "mma.sync.aligned.m16n8k8.row.col.f32.tf32.tf32.f32 "
        "{%0,%1,%2,%3}, {%4,%5,%6,%7}, {%8,%9}, {%0,%1,%2,%3};"
        : "+f"(c[0]), "+f"(c[1]), "+f"(c[2]), "+f"(c[3])
        : "r"(a[0]), "r"(a[1]), "r"(a[2]), "r"(a[3]), "r"(b[0]), "r"(b[1]));
}

// ---------------------------------------------------------------------------
// TF32 mma.sync GEMM. Block tile 128x128, BK=32, 3-stage cp.async,
// ONE __syncthreads per K-iteration. 8 warps as 2(M) x 4(N), warp tile 64x32.
// MODE 0: C[4096,2304] = Xw @ [Wq;Wk;Wv]^T + bias -> g_qkv[which][b][h][s][d]
//         grid is 1D, 768 blocks: every 4th block is a tail-copy block.
// MODE 1: C[4096, 768] = O  @ Wo^T         + bo   -> d_out[b][s][c] (s < 64)
// ---------------------------------------------------------------------------
#define BK   32
#define LDK  36                         // 32 + 4: 16B-aligned rows, conflict-free frags
#define STAGEF ((128 + 128) * LDK)      // 9216 floats / stage
#define NSTG 3
#define DSMEM  (NSTG * STAGEF * 4)      // 110592 B -> 2 CTAs/SM
#define NKI  (PF / BK)                  // 24

#define NCOPY 192
#define CCHUNK 61440                    // float4 per copy block; 192*61440 = 64*960*192

template <int MODE>
__global__ void __launch_bounds__(256, 2) tc_gemm(
    const float* __restrict__ A,
    const float* __restrict__ W0, const float* __restrict__ W1, const float* __restrict__ W2,
    const float* __restrict__ b0, const float* __restrict__ b1, const float* __restrict__ b2,
    float* __restrict__ Cout)
{
    extern __shared__ float sm[];

    const int tid  = threadIdx.x;
    int bid = blockIdx.x;

    if (MODE == 0) {
        // Every 4th block streams a slice of x[:,64:,:] -> out[:,64:,:]
        if ((bid & 3) == 3) {
            int cb = bid >> 2;                       // 0..191
            const float4* src = (const float4*)A;
            float4* dst = (float4*)Cout;
            const int PERB = (PS - PP2) * (PF / 4);  // 184320
            int base = cb * CCHUNK;
            #pragma unroll 4
            for (int t = tid; t < CCHUNK; t += 256) {
                int i = base + t;
                int b = i / PERB;
                int rem = i - b * PERB;
                long long off = (long long)b * (PS * (PF / 4)) + PP2 * (PF / 4) + rem;
                __stcs(dst + off, __ldcs(src + off));
            }
            return;
        }
        bid -= (bid >> 2);               // compact to 0..575
    }

    const int wid  = tid >> 5;
    const int lane = tid & 31;
    const int wm   = wid >> 2;           // 0..1
    const int wn   = wid & 3;            // 0..3
    const int g    = lane >> 2;          // 0..7
    const int t4   = lane & 3;           // 0..3

    const int m0 = (bid & 31) * 128;
    const int ny = (MODE == 0) ? (bid >> 5) : (bid >> 5);   // n-tile index

    const float* W; const float* bias; int nbw; int wsel = 0;
    if (MODE == 0) {
        wsel = ny / 6;
        nbw  = (ny % 6) * 128;
        W    = (wsel == 0) ? W0 : (wsel == 1 ? W1 : W2);
        bias = (wsel == 0) ? b0 : (wsel == 1 ? b1 : b2);
    } else {
        W = W0; bias = b0; nbw = ny * 128;
    }
    const float* Ap = (MODE == 0) ? A : g_o;

    // Stage loader: A 128x32 + B 128x32, 4+4 cp16 per thread
    auto load_stage = [&](int buf, int k0) {
        float* As = sm + buf * STAGEF;
        float* Bs = As + 128 * LDK;
        #pragma unroll
        for (int p = 0; p < 4; p++) {
            int idx = tid + p * 256;
            int r = idx >> 3, c4 = (idx & 7) * 4;
            int gm = m0 + r;
            const float* ga = (MODE == 0)
                ? Ap + ((long long)(gm >> 6) * PS + (gm & 63)) * PF + k0 + c4
                : Ap + (long long)gm * PF + k0 + c4;
            cp16(&As[r * LDK + c4], ga);
        }
        #pragma unroll
        for (int p = 0; p < 4; p++) {
            int idx = tid + p * 256;
            int r = idx >> 3, c4 = (idx & 7) * 4;
            const float* gb = W + (long long)(nbw + r) * PF + k0 + c4;
            cp16(&Bs[r * LDK + c4], gb);
        }
    };

    float acc[4][4][4];
    #pragma unroll
    for (int mi = 0; mi < 4; mi++)
        #pragma unroll
        for (int ni = 0; ni < 4; ni++)
            #pragma unroll
            for (int q = 0; q < 4; q++) acc[mi][ni][q] = 0.0f;

    load_stage(0, 0);
    cp_commit();
    load_stage(1, BK);
    cp_commit();

    int buf = 0;
    for (int i = 0; i < NKI; i++) {
        if (i < NKI - 1) { cp_wait<1>(); } else { cp_wait<0>(); }
        __syncthreads();
        if (i + 2 < NKI) {
            int lb = buf + 2; if (lb >= NSTG) lb -= NSTG;
            load_stage(lb, (i + 2) * BK);
            cp_commit();
        }

        const float* As = sm + buf * STAGEF;
        const float* Bs = As + 128 * LDK;
        const float* ab = As + (wm * 64 + g) * LDK + t4;
        const float* bb = Bs + (wn * 32 + g) * LDK + t4;

        #pragma unroll
        for (int kk = 0; kk < BK; kk += 8) {
            unsigned af[4][4];
            #pragma unroll
            for (int mi = 0; mi < 4; mi++) {
                const float* p = ab + mi * 16 * LDK + kk;
                af[mi][0] = __float_as_uint(p[0]);
                af[mi][1] = __float_as_uint(p[8 * LDK]);
                af[mi][2] = __float_as_uint(p[4]);
                af[mi][3] = __float_as_uint(p[8 * LDK + 4]);
            }
            unsigned bf[4][2];
            #pragma unroll
            for (int ni = 0; ni < 4; ni++) {
                const float* p = bb + ni * 8 * LDK + kk;
                bf[ni][0] = __float_as_uint(p[0]);
                bf[ni][1] = __float_as_uint(p[4]);
            }
            #pragma unroll
            for (int mi = 0; mi < 4; mi++)
                #pragma unroll
                for (int ni = 0; ni < 4; ni++)
                    mma_tf32(acc[mi][ni], af[mi], bf[ni]);
        }

        buf++; if (buf >= NSTG) buf -= NSTG;
    }

    // Bias per ni (float2, col pair this thread owns)
    float2 bfrag[4];
    #pragma unroll
    for (int ni = 0; ni < 4; ni++)
        bfrag[ni] = *reinterpret_cast<const float2*>(bias + nbw + wn * 32 + ni * 8 + t4 * 2);

    // Epilogue: direct global float2 stores from accumulators
    #pragma unroll
    for (int mi = 0; mi < 4; mi++) {
        #pragma unroll
        for (int half = 0; half < 2; half++) {
            int gm = m0 + wm * 64 + mi * 16 + g + half * 8;
            int bb_ = gm >> 6, ss_ = gm & 63;
            #pragma unroll
            for (int ni = 0; ni < 4; ni++) {
                int n = nbw + wn * 32 + ni * 8 + t4 * 2;
                float2 v;
                v.x = acc[mi][ni][half * 2 + 0] + bfrag[ni].x;
                v.y = acc[mi][ni][half * 2 + 1] + bfrag[ni].y;
                if (MODE == 0) {
                    int h = n >> 6, d = n & 63;
                    float* dst = g_qkv + (long long)wsel * QKVSTRIDE
                               + (long long)(bb_ * PH + h) * HEADSZ + ss_ * 64 + d;
                    *reinterpret_cast<float2*>(dst) = v;
                } else {
                    float* dst = Cout + ((long long)bb_ * PS + ss_) * PF + n;
                    *reinterpret_cast<float2*>(dst) = v;
                }
            }
        }
    }
}

// ---------------------------------------------------------------------------
// Attention, one block per (b,h). 64x64 q,k,v tiles in smem.
// ---------------------------------------------------------------------------
__global__ void __launch_bounds__(256) attn_kernel() {
    __shared__ float sq[64 * 64];
    __shared__ float sk[64 * 64];
    __shared__ float ss[64 * 64];

    const int tid = threadIdx.x;
    const int b = blockIdx.x / PH;
    const int h = blockIdx.x % PH;
    const float* qg = g_qkv + (long long)(b * PH + h) * HEADSZ;
    const float* kg = qg + (long long)QKVSTRIDE;
    const float* vg = kg + (long long)QKVSTRIDE;
    const int lane = tid & 31;

    for (int t = tid; t < 1024; t += 256)
        reinterpret_cast<float4*>(sq)[t] = reinterpret_cast<const float4*>(qg)[t];
    for (int t = tid; t < 1024; t += 256) {
        int j = t >> 4, d4 = (t & 15) * 4;
        float4 v = reinterpret_cast<const float4*>(kg)[t];
        *reinterpret_cast<float4*>(&sk[j * 64 + (d4 ^ ((j & 7) << 3))]) = v;
    }
    __syncthreads();

    #pragma unroll
    for (int t = 0; t < 16; t++) {
        int idx = tid + (t << 8);
        int i = idx >> 6, j = idx & 63;
        int sw = (j & 7) << 3;
        float s = 0.f;
        #pragma unroll
        for (int dd = 0; dd < 64; dd += 4) {
            float4 q4 = *reinterpret_cast<const float4*>(&sq[i * 64 + dd]);
            float4 k4 = *reinterpret_cast<const float4*>(&sk[j * 64 + (dd ^ sw)]);
            s += q4.x * k4.x + q4.y * k4.y + q4.z * k4.z + q4.w * k4.w;
        }
        ss[idx] = s * 0.125f;
    }
    __syncthreads();

    {
        int w = tid >> 5;
        #pragma unroll
        for (int rr = 0; rr < 8; rr++) {
            int i = w * 8 + rr;
            float x0 = ss[i * 64 + lane];
            float x1 = ss[i * 64 + 32 + lane];
            float m = fmaxf(x0, x1);
            #pragma unroll
            for (int o = 16; o; o >>= 1) m = fmaxf(m, __shfl_xor_sync(0xffffffffu, m, o));
            float e0 = __expf(x0 - m), e1 = __expf(x1 - m);
            float sum = e0 + e1;
            #pragma unroll
            for (int o = 16; o; o >>= 1) sum += __shfl_xor_sync(0xffffffffu, sum, o);
            float inv = 1.0f / sum;
            ss[i * 64 + lane]      = e0 * inv;
            ss[i * 64 + 32 + lane] = e1 * inv;
        }
    }
    __syncthreads();

    for (int t = tid; t < 1024; t += 256)
        reinterpret_cast<float4*>(sq)[t] = reinterpret_cast<const float4*>(vg)[t];
    __syncthreads();

    #pragma unroll
    for (int t = 0; t < 4; t++) {
        int gidx = tid + (t << 8);
        int i  = gidx >> 4;
        int d4 = (gidx & 15) * 4;
        float ox = 0.f, oy = 0.f, oz = 0.f, ow = 0.f;
        #pragma unroll 16
        for (int j = 0; j < 64; j++) {
            float a = ss[i * 64 + j];
            float4 v4 = *reinterpret_cast<const float4*>(&sq[j * 64 + d4]);
            ox += a * v4.x; oy += a * v4.y; oz += a * v4.z; ow += a * v4.w;
        }
        float4 o4; o4.x = ox; o4.y = oy; o4.z = oz; o4.w = ow;
        *reinterpret_cast<float4*>(&g_o[(long long)(b * 64 + i) * PF + h * 64 + d4]) = o4;
    }
}

// ---------------------------------------------------------------------------
extern "C" void kernel_launch(void* const* d_in, const int* in_sizes, int n_in,
                              void* d_out, int out_size) {
    const float* x  = (const float*)d_in[0];
    const float* Wq = (const float*)d_in[1];
    const float* bq = (const float*)d_in[2];
    const float* Wk = (const float*)d_in[3];
    const float* bk = (const float*)d_in[4];
    const float* Wv = (const float*)d_in[5];
    const float* bv = (const float*)d_in[6];
    const float* Wo = (const float*)d_in[7];
    const float* bo = (const float*)d_in[8];
    float* out = (float*)d_out;

    cudaFuncSetAttribute(tc_gemm<0>, cudaFuncAttributeMaxDynamicSharedMemorySize, DSMEM);
    cudaFuncSetAttribute(tc_gemm<1>, cudaFuncAttributeMaxDynamicSharedMemorySize, DSMEM);

    // 1) QKV projection (+bias) into g_qkv, with interleaved tail-copy blocks
    //    576 gemm blocks + 192 copy blocks (every 4th)
    tc_gemm<0><<<768, 256, DSMEM>>>(x, Wq, Wk, Wv, bq, bk, bv, out);

    // 2) attention per (b,h)
    attn_kernel<<<PB * PH, 256>>>();

    // 3) output projection (+bo) into d_out[:, :64, :]: 192 blocks
    tc_gemm<1><<<192, 256, DSMEM>>>(nullptr, Wo, nullptr, nullptr,
                                    bo, nullptr, nullptr, out);
}

// round 9
// speedup vs baseline: 1.0008x; 1.0002x over previous
#include <cuda_runtime.h>
#include <cstdint>

// Problem constants
#define PB   64
#define PS   1024
#define PF   768
#define PH   12
#define PP2  64
#define HEADSZ 4096
#define QKVSTRIDE (PB * PH * HEADSZ)   // 3,145,728

__device__ float g_qkv[3LL * QKVSTRIDE];
__device__ float g_o[4096LL * PF];

// ---------------------------------------------------------------------------
// PTX helpers
// ---------------------------------------------------------------------------
__device__ __forceinline__ void cp16(void* s, const void* g) {
    unsigned sa = (unsigned)__cvta_generic_to_shared(s);
    asm volatile("cp.async.cg.shared.global [%0], [%1], 16;\n" :: "r"(sa), "l"(g));
}
__device__ __forceinline__ void cp_commit() { asm volatile("cp.async.commit_group;\n"); }
template <int N>
__device__ __forceinline__ void cp_wait() { asm volatile("cp.async.wait_group %0;\n" :: "n"(N)); }

__device__ __forceinline__ void mma_tf32(float* c, const unsigned* a, const unsigned* b) {
    asm volatile(
        "mma.sync.aligned.m16n8k8.row.col.f32.tf32.tf32.f32 "
        "{%0,%1,%2,%3}, {%4,%5,%6,%7}, {%8,%9}, {%0,%1,%2,%3};"
        : "+f"(c[0]), "+f"(c[1]), "+f"(c[2]), "+f"(c[3])
        : "r"(a[0]), "r"(a[1]), "r"(a[2]), "r"(a[3]), "r"(b[0]), "r"(b[1]));
}

// ---------------------------------------------------------------------------
// TF32 mma.sync GEMM. Block tile 128x128, BK=32, 3-stage cp.async,
// ONE __syncthreads per K-iteration. 8 warps as 2(M) x 4(N), warp tile 64x32.
// MODE 0: C[4096,2304] = Xw @ [Wq;Wk;Wv]^T + bias -> g_qkv[which][b][h][s][d]
//         grid is 1D, 768 blocks: every 4th block is a tail-copy block.
// MODE 1: C[4096, 768] = O  @ Wo^T         + bo   -> d_out[b][s][c] (s < 64)
// ---------------------------------------------------------------------------
#define BK   32
#define LDK  36                         // 32 + 4: 16B-aligned rows, conflict-free frags
#define STAGEF ((128 + 128) * LDK)      // 9216 floats / stage
#define NSTG 3
#define DSMEM  (NSTG * STAGEF * 4)      // 110592 B -> 2 CTAs/SM
#define NKI  (PF / BK)                  // 24

#define NCOPY 192
#define CCHUNK 61440                    // float4 per copy block; 192*61440 = 64*960*192

template <int MODE>
__global__ void __launch_bounds__(256, 2) tc_gemm(
    const float* __restrict__ A,
    const float* __restrict__ W0, const float* __restrict__ W1, const float* __restrict__ W2,
    const float* __restrict__ b0, const float* __restrict__ b1, const float* __restrict__ b2,
    float* __restrict__ Cout)
{
    extern __shared__ float sm[];

    const int tid  = threadIdx.x;
    int bid = blockIdx.x;

    if (MODE == 0) {
        // Every 4th block streams a slice of x[:,64:,:] -> out[:,64:,:]
        if ((bid & 3) == 3) {
            int cb = bid >> 2;                       // 0..191
            const float4* src = (const float4*)A;
            float4* dst = (float4*)Cout;
            const int PERB = (PS - PP2) * (PF / 4);  // 184320
            int base = cb * CCHUNK;
            #pragma unroll 4
            for (int t = tid; t < CCHUNK; t += 256) {
                int i = base + t;
                int b = i / PERB;
                int rem = i - b * PERB;
                long long off = (long long)b * (PS * (PF / 4)) + PP2 * (PF / 4) + rem;
                __stcs(dst + off, __ldcs(src + off));
            }
            return;
        }
        bid -= (bid >> 2);               // compact to 0..575
    }

    const int wid  = tid >> 5;
    const int lane = tid & 31;
    const int wm   = wid >> 2;           // 0..1
    const int wn   = wid & 3;            // 0..3
    const int g    = lane >> 2;          // 0..7
    const int t4   = lane & 3;           // 0..3

    const int m0 = (bid & 31) * 128;
    const int ny = (MODE == 0) ? (bid >> 5) : (bid >> 5);   // n-tile index

    const float* W; const float* bias; int nbw; int wsel = 0;
    if (MODE == 0) {
        wsel = ny / 6;
        nbw  = (ny % 6) * 128;
        W    = (wsel == 0) ? W0 : (wsel == 1 ? W1 : W2);
        bias = (wsel == 0) ? b0 : (wsel == 1 ? b1 : b2);
    } else {
        W = W0; bias = b0; nbw = ny * 128;
    }
    const float* Ap = (MODE == 0) ? A : g_o;

    // Stage loader: A 128x32 + B 128x32, 4+4 cp16 per thread
    auto load_stage = [&](int buf, int k0) {
        float* As = sm + buf * STAGEF;
        float* Bs = As + 128 * LDK;
        #pragma unroll
        for (int p = 0; p < 4; p++) {
            int idx = tid + p * 256;
            int r = idx >> 3, c4 = (idx & 7) * 4;
            int gm = m0 + r;
            const float* ga = (MODE == 0)
                ? Ap + ((long long)(gm >> 6) * PS + (gm & 63)) * PF + k0 + c4
                : Ap + (long long)gm * PF + k0 + c4;
            cp16(&As[r * LDK + c4], ga);
        }
        #pragma unroll
        for (int p = 0; p < 4; p++) {
            int idx = tid + p * 256;
            int r = idx >> 3, c4 = (idx & 7) * 4;
            const float* gb = W + (long long)(nbw + r) * PF + k0 + c4;
            cp16(&Bs[r * LDK + c4], gb);
        }
    };

    float acc[4][4][4];
    #pragma unroll
    for (int mi = 0; mi < 4; mi++)
        #pragma unroll
        for (int ni = 0; ni < 4; ni++)
            #pragma unroll
            for (int q = 0; q < 4; q++) acc[mi][ni][q] = 0.0f;

    load_stage(0, 0);
    cp_commit();
    load_stage(1, BK);
    cp_commit();

    int buf = 0;
    for (int i = 0; i < NKI; i++) {
        if (i < NKI - 1) { cp_wait<1>(); } else { cp_wait<0>(); }
        __syncthreads();
        if (i + 2 < NKI) {
            int lb = buf + 2; if (lb >= NSTG) lb -= NSTG;
            load_stage(lb, (i + 2) * BK);
            cp_commit();
        }

        const float* As = sm + buf * STAGEF;
        const float* Bs = As + 128 * LDK;
        const float* ab = As + (wm * 64 + g) * LDK + t4;
        const float* bb = Bs + (wn * 32 + g) * LDK + t4;

        #pragma unroll
        for (int kk = 0; kk < BK; kk += 8) {
            unsigned af[4][4];
            #pragma unroll
            for (int mi = 0; mi < 4; mi++) {
                const float* p = ab + mi * 16 * LDK + kk;
                af[mi][0] = __float_as_uint(p[0]);
                af[mi][1] = __float_as_uint(p[8 * LDK]);
                af[mi][2] = __float_as_uint(p[4]);
                af[mi][3] = __float_as_uint(p[8 * LDK + 4]);
            }
            unsigned bf[4][2];
            #pragma unroll
            for (int ni = 0; ni < 4; ni++) {
                const float* p = bb + ni * 8 * LDK + kk;
                bf[ni][0] = __float_as_uint(p[0]);
                bf[ni][1] = __float_as_uint(p[4]);
            }
            #pragma unroll
            for (int mi = 0; mi < 4; mi++)
                #pragma unroll
                for (int ni = 0; ni < 4; ni++)
                    mma_tf32(acc[mi][ni], af[mi], bf[ni]);
        }

        buf++; if (buf >= NSTG) buf -= NSTG;
    }

    // Bias per ni (float2, col pair this thread owns)
    float2 bfrag[4];
    #pragma unroll
    for (int ni = 0; ni < 4; ni++)
        bfrag[ni] = *reinterpret_cast<const float2*>(bias + nbw + wn * 32 + ni * 8 + t4 * 2);

    // Epilogue: direct global float2 stores from accumulators
    #pragma unroll
    for (int mi = 0; mi < 4; mi++) {
        #pragma unroll
        for (int half = 0; half < 2; half++) {
            int gm = m0 + wm * 64 + mi * 16 + g + half * 8;
            int bb_ = gm >> 6, ss_ = gm & 63;
            #pragma unroll
            for (int ni = 0; ni < 4; ni++) {
                int n = nbw + wn * 32 + ni * 8 + t4 * 2;
                float2 v;
                v.x = acc[mi][ni][half * 2 + 0] + bfrag[ni].x;
                v.y = acc[mi][ni][half * 2 + 1] + bfrag[ni].y;
                if (MODE == 0) {
                    int h = n >> 6, d = n & 63;
                    float* dst = g_qkv + (long long)wsel * QKVSTRIDE
                               + (long long)(bb_ * PH + h) * HEADSZ + ss_ * 64 + d;
                    *reinterpret_cast<float2*>(dst) = v;
                } else {
                    float* dst = Cout + ((long long)bb_ * PS + ss_) * PF + n;
                    *reinterpret_cast<float2*>(dst) = v;
                }
            }
        }
    }
}

// ---------------------------------------------------------------------------
// Attention, one block per (b,h). 64x64 q,k,v tiles in smem.
// ---------------------------------------------------------------------------
__global__ void __launch_bounds__(256) attn_kernel() {
    __shared__ float sq[64 * 64];
    __shared__ float sk[64 * 64];
    __shared__ float ss[64 * 64];

    const int tid = threadIdx.x;
    const int b = blockIdx.x / PH;
    const int h = blockIdx.x % PH;
    const float* qg = g_qkv + (long long)(b * PH + h) * HEADSZ;
    const float* kg = qg + (long long)QKVSTRIDE;
    const float* vg = kg + (long long)QKVSTRIDE;
    const int lane = tid & 31;

    for (int t = tid; t < 1024; t += 256)
        reinterpret_cast<float4*>(sq)[t] = reinterpret_cast<const float4*>(qg)[t];
    for (int t = tid; t < 1024; t += 256) {
        int j = t >> 4, d4 = (t & 15) * 4;
        float4 v = reinterpret_cast<const float4*>(kg)[t];
        *reinterpret_cast<float4*>(&sk[j * 64 + (d4 ^ ((j & 7) << 3))]) = v;
    }
    __syncthreads();

    #pragma unroll
    for (int t = 0; t < 16; t++) {
        int idx = tid + (t << 8);
        int i = idx >> 6, j = idx & 63;
        int sw = (j & 7) << 3;
        float s = 0.f;
        #pragma unroll
        for (int dd = 0; dd < 64; dd += 4) {
            float4 q4 = *reinterpret_cast<const float4*>(&sq[i * 64 + dd]);
            float4 k4 = *reinterpret_cast<const float4*>(&sk[j * 64 + (dd ^ sw)]);
            s += q4.x * k4.x + q4.y * k4.y + q4.z * k4.z + q4.w * k4.w;
        }
        ss[idx] = s * 0.125f;
    }
    __syncthreads();

    {
        int w = tid >> 5;
        #pragma unroll
        for (int rr = 0; rr < 8; rr++) {
            int i = w * 8 + rr;
            float x0 = ss[i * 64 + lane];
            float x1 = ss[i * 64 + 32 + lane];
            float m = fmaxf(x0, x1);
            #pragma unroll
            for (int o = 16; o; o >>= 1) m = fmaxf(m, __shfl_xor_sync(0xffffffffu, m, o));
            float e0 = __expf(x0 - m), e1 = __expf(x1 - m);
            float sum = e0 + e1;
            #pragma unroll
            for (int o = 16; o; o >>= 1) sum += __shfl_xor_sync(0xffffffffu, sum, o);
            float inv = 1.0f / sum;
            ss[i * 64 + lane]      = e0 * inv;
            ss[i * 64 + 32 + lane] = e1 * inv;
        }
    }
    __syncthreads();

    for (int t = tid; t < 1024; t += 256)
        reinterpret_cast<float4*>(sq)[t] = reinterpret_cast<const float4*>(vg)[t];
    __syncthreads();

    #pragma unroll
    for (int t = 0; t < 4; t++) {
        int gidx = tid + (t << 8);
        int i  = gidx >> 4;
        int d4 = (gidx & 15) * 4;
        float ox = 0.f, oy = 0.f, oz = 0.f, ow = 0.f;
        #pragma unroll 16
        for (int j = 0; j < 64; j++) {
            float a = ss[i * 64 + j];
            float4 v4 = *reinterpret_cast<const float4*>(&sq[j * 64 + d4]);
            ox += a * v4.x; oy += a * v4.y; oz += a * v4.z; ow += a * v4.w;
        }
        float4 o4; o4.x = ox; o4.y = oy; o4.z = oz; o4.w = ow;
        *reinterpret_cast<float4*>(&g_o[(long long)(b * 64 + i) * PF + h * 64 + d4]) = o4;
    }
}

// ---------------------------------------------------------------------------
extern "C" void kernel_launch(void* const* d_in, const int* in_sizes, int n_in,
                              void* d_out, int out_size) {
    const float* x  = (const float*)d_in[0];
    const float* Wq = (const float*)d_in[1];
    const float* bq = (const float*)d_in[2];
    const float* Wk = (const float*)d_in[3];
    const float* bk = (const float*)d_in[4];
    const float* Wv = (const float*)d_in[5];
    const float* bv = (const float*)d_in[6];
    const float* Wo = (const float*)d_in[7];
    const float* bo = (const float*)d_in[8];
    float* out = (float*)d_out;

    cudaFuncSetAttribute(tc_gemm<0>, cudaFuncAttributeMaxDynamicSharedMemorySize, DSMEM);
    cudaFuncSetAttribute(tc_gemm<1>, cudaFuncAttributeMaxDynamicSharedMemorySize, DSMEM);

    // 1) QKV projection (+bias) into g_qkv, with interleaved tail-copy blocks
    //    576 gemm blocks + 192 copy blocks (every 4th)
    tc_gemm<0><<<768, 256, DSMEM>>>(x, Wq, Wk, Wv, bq, bk, bv, out);

    // 2) attention per (b,h)
    attn_kernel<<<PB * PH, 256>>>();

    // 3) output projection (+bo) into d_out[:, :64, :]: 192 blocks
    tc_gemm<1><<<192, 256, DSMEM>>>(nullptr, Wo, nullptr, nullptr,
                                    bo, nullptr, nullptr, out);
}

// round 10
// speedup vs baseline: 1.0021x; 1.0013x over previous
#include <cuda_runtime.h>
#include <cstdint>

// Problem constants
#define PB   64
#define PS   1024
#define PF   768
#define PH   12
#define PP2  64
#define HEADSZ 4096
#define QKVSTRIDE (PB * PH * HEADSZ)   // 3,145,728

__device__ float g_qkv[3LL * QKVSTRIDE];
__device__ float g_o[4096LL * PF];

// ---------------------------------------------------------------------------
// PTX helpers
// ---------------------------------------------------------------------------
__device__ __forceinline__ void cp16(void* s, const void* g) {
    unsigned sa = (unsigned)__cvta_generic_to_shared(s);
    asm volatile("cp.async.cg.shared.global [%0], [%1], 16;\n" :: "r"(sa), "l"(g));
}
__device__ __forceinline__ void cp_commit() { asm volatile("cp.async.commit_group;\n"); }
template <int N>
__device__ __forceinline__ void cp_wait() { asm volatile("cp.async.wait_group %0;\n" :: "n"(N)); }

__device__ __forceinline__ void mma_tf32(float* c, const unsigned* a, const unsigned* b) {
    asm volatile(
        "mma.sync.aligned.m16n8k8.row.col.f32.tf32.tf32.f32 "
        "{%0,%1,%2,%3}, {%4,%5,%6,%7}, {%8,%9}, {%0,%1,%2,%3};"
        : "+f"(c[0]), "+f"(c[1]), "+f"(c[2]), "+f"(c[3])
        : "r"(a[0]), "r"(a[1]), "r"(a[2]), "r"(a[3]), "r"(b[0]), "r"(b[1]));
}

// ---------------------------------------------------------------------------
// TF32 mma.sync GEMM. Block tile 128x128, BK=32, 3-stage cp.async,
// ONE __syncthreads per K-iteration. 8 warps as 2(M) x 4(N), warp tile 64x32.
// MODE 0: C[4096,2304] = Xw @ [Wq;Wk;Wv]^T + bias -> g_qkv[which][b][h][s][d]
//         grid is 1D, 768 blocks: every 4th block is a tail-copy block.
// MODE 1: C[4096, 768] = O  @ Wo^T         + bo   -> d_out[b][s][c] (s < 64)
// ---------------------------------------------------------------------------
#define BK   32
#define LDK  36                         // 32 + 4: 16B-aligned rows, conflict-free frags
#define STAGEF ((128 + 128) * LDK)      // 9216 floats / stage
#define NSTG 3
#define DSMEM  (NSTG * STAGEF * 4)      // 110592 B -> 2 CTAs/SM
#define NKI  (PF / BK)                  // 24

#define NCOPY 192
#define CCHUNK 61440                    // float4 per copy block; 192*61440 = 64*960*192

template <int MODE>
__global__ void __launch_bounds__(256, 2) tc_gemm(
    const float* __restrict__ A,
    const float* __restrict__ W0, const float* __restrict__ W1, const float* __restrict__ W2,
    const float* __restrict__ b0, const float* __restrict__ b1, const float* __restrict__ b2,
    float* __restrict__ Cout)
{
    extern __shared__ float sm[];

    const int tid  = threadIdx.x;
    int bid = blockIdx.x;

    if (MODE == 0) {
        // Every 4th block streams a slice of x[:,64:,:] -> out[:,64:,:]
        if ((bid & 3) == 3) {
            int cb = bid >> 2;                       // 0..191
            const float4* src = (const float4*)A;
            float4* dst = (float4*)Cout;
            const int PERB = (PS - PP2) * (PF / 4);  // 184320
            int base = cb * CCHUNK;
            #pragma unroll 4
            for (int t = tid; t < CCHUNK; t += 256) {
                int i = base + t;
                int b = i / PERB;
                int rem = i - b * PERB;
                long long off = (long long)b * (PS * (PF / 4)) + PP2 * (PF / 4) + rem;
                __stcs(dst + off, __ldcs(src + off));
            }
            return;
        }
        bid -= (bid >> 2);               // compact to 0..575
    }

    const int wid  = tid >> 5;
    const int lane = tid & 31;
    const int wm   = wid >> 2;           // 0..1
    const int wn   = wid & 3;            // 0..3
    const int g    = lane >> 2;          // 0..7
    const int t4   = lane & 3;           // 0..3

    const int m0 = (bid & 31) * 128;
    const int ny = (MODE == 0) ? (bid >> 5) : (bid >> 5);   // n-tile index

    const float* W; const float* bias; int nbw; int wsel = 0;
    if (MODE == 0) {
        wsel = ny / 6;
        nbw  = (ny % 6) * 128;
        W    = (wsel == 0) ? W0 : (wsel == 1 ? W1 : W2);
        bias = (wsel == 0) ? b0 : (wsel == 1 ? b1 : b2);
    } else {
        W = W0; bias = b0; nbw = ny * 128;
    }
    const float* Ap = (MODE == 0) ? A : g_o;

    // Stage loader: A 128x32 + B 128x32, 4+4 cp16 per thread
    auto load_stage = [&](int buf, int k0) {
        float* As = sm + buf * STAGEF;
        float* Bs = As + 128 * LDK;
        #pragma unroll
        for (int p = 0; p < 4; p++) {
            int idx = tid + p * 256;
            int r = idx >> 3, c4 = (idx & 7) * 4;
            int gm = m0 + r;
            const float* ga = (MODE == 0)
                ? Ap + ((long long)(gm >> 6) * PS + (gm & 63)) * PF + k0 + c4
                : Ap + (long long)gm * PF + k0 + c4;
            cp16(&As[r * LDK + c4], ga);
        }
        #pragma unroll
        for (int p = 0; p < 4; p++) {
            int idx = tid + p * 256;
            int r = idx >> 3, c4 = (idx & 7) * 4;
            const float* gb = W + (long long)(nbw + r) * PF + k0 + c4;
            cp16(&Bs[r * LDK + c4], gb);
        }
    };

    float acc[4][4][4];
    #pragma unroll
    for (int mi = 0; mi < 4; mi++)
        #pragma unroll
        for (int ni = 0; ni < 4; ni++)
            #pragma unroll
            for (int q = 0; q < 4; q++) acc[mi][ni][q] = 0.0f;

    load_stage(0, 0);
    cp_commit();
    load_stage(1, BK);
    cp_commit();

    int buf = 0;
    for (int i = 0; i < NKI; i++) {
        if (i < NKI - 1) { cp_wait<1>(); } else { cp_wait<0>(); }
        __syncthreads();
        if (i + 2 < NKI) {
            int lb = buf + 2; if (lb >= NSTG) lb -= NSTG;
            load_stage(lb, (i + 2) * BK);
            cp_commit();
        }

        const float* As = sm + buf * STAGEF;
        const float* Bs = As + 128 * LDK;
        const float* ab = As + (wm * 64 + g) * LDK + t4;
        const float* bb = Bs + (wn * 32 + g) * LDK + t4;

        #pragma unroll
        for (int kk = 0; kk < BK; kk += 8) {
            unsigned af[4][4];
            #pragma unroll
            for (int mi = 0; mi < 4; mi++) {
                const float* p = ab + mi * 16 * LDK + kk;
                af[mi][0] = __float_as_uint(p[0]);
                af[mi][1] = __float_as_uint(p[8 * LDK]);
                af[mi][2] = __float_as_uint(p[4]);
                af[mi][3] = __float_as_uint(p[8 * LDK + 4]);
            }
            unsigned bf[4][2];
            #pragma unroll
            for (int ni = 0; ni < 4; ni++) {
                const float* p = bb + ni * 8 * LDK + kk;
                bf[ni][0] = __float_as_uint(p[0]);
                bf[ni][1] = __float_as_uint(p[4]);
            }
            #pragma unroll
            for (int mi = 0; mi < 4; mi++)
                #pragma unroll
                for (int ni = 0; ni < 4; ni++)
                    mma_tf32(acc[mi][ni], af[mi], bf[ni]);
        }

        buf++; if (buf >= NSTG) buf -= NSTG;
    }

    // Bias per ni (float2, col pair this thread owns)
    float2 bfrag[4];
    #pragma unroll
    for (int ni = 0; ni < 4; ni++)
        bfrag[ni] = *reinterpret_cast<const float2*>(bias + nbw + wn * 32 + ni * 8 + t4 * 2);

    // Epilogue: direct global float2 stores from accumulators
    #pragma unroll
    for (int mi = 0; mi < 4; mi++) {
        #pragma unroll
        for (int half = 0; half < 2; half++) {
            int gm = m0 + wm * 64 + mi * 16 + g + half * 8;
            int bb_ = gm >> 6, ss_ = gm & 63;
            #pragma unroll
            for (int ni = 0; ni < 4; ni++) {
                int n = nbw + wn * 32 + ni * 8 + t4 * 2;
                float2 v;
                v.x = acc[mi][ni][half * 2 + 0] + bfrag[ni].x;
                v.y = acc[mi][ni][half * 2 + 1] + bfrag[ni].y;
                if (MODE == 0) {
                    int h = n >> 6, d = n & 63;
                    float* dst = g_qkv + (long long)wsel * QKVSTRIDE
                               + (long long)(bb_ * PH + h) * HEADSZ + ss_ * 64 + d;
                    *reinterpret_cast<float2*>(dst) = v;
                } else {
                    float* dst = Cout + ((long long)bb_ * PS + ss_) * PF + n;
                    *reinterpret_cast<float2*>(dst) = v;
                }
            }
        }
    }
}

// ---------------------------------------------------------------------------
// Attention, one block per (b,h). 64x64 q,k,v tiles in smem.
// ---------------------------------------------------------------------------
__global__ void __launch_bounds__(256) attn_kernel() {
    __shared__ float sq[64 * 64];
    __shared__ float sk[64 * 64];
    __shared__ float ss[64 * 64];

    const int tid = threadIdx.x;
    const int b = blockIdx.x / PH;
    const int h = blockIdx.x % PH;
    const float* qg = g_qkv + (long long)(b * PH + h) * HEADSZ;
    const float* kg = qg + (long long)QKVSTRIDE;
    const float* vg = kg + (long long)QKVSTRIDE;
    const int lane = tid & 31;

    for (int t = tid; t < 1024; t += 256)
        reinterpret_cast<float4*>(sq)[t] = reinterpret_cast<const float4*>(qg)[t];
    for (int t = tid; t < 1024; t += 256) {
        int j = t >> 4, d4 = (t & 15) * 4;
        float4 v = reinterpret_cast<const float4*>(kg)[t];
        *reinterpret_cast<float4*>(&sk[j * 64 + (d4 ^ ((j & 7) << 3))]) = v;
    }
    __syncthreads();

    #pragma unroll
    for (int t = 0; t < 16; t++) {
        int idx = tid + (t << 8);
        int i = idx >> 6, j = idx & 63;
        int sw = (j & 7) << 3;
        float s = 0.f;
        #pragma unroll
        for (int dd = 0; dd < 64; dd += 4) {
            float4 q4 = *reinterpret_cast<const float4*>(&sq[i * 64 + dd]);
            float4 k4 = *reinterpret_cast<const float4*>(&sk[j * 64 + (dd ^ sw)]);
            s += q4.x * k4.x + q4.y * k4.y + q4.z * k4.z + q4.w * k4.w;
        }
        ss[idx] = s * 0.125f;
    }
    __syncthreads();

    {
        int w = tid >> 5;
        #pragma unroll
        for (int rr = 0; rr < 8; rr++) {
            int i = w * 8 + rr;
            float x0 = ss[i * 64 + lane];
            float x1 = ss[i * 64 + 32 + lane];
            float m = fmaxf(x0, x1);
            #pragma unroll
            for (int o = 16; o; o >>= 1) m = fmaxf(m, __shfl_xor_sync(0xffffffffu, m, o));
            float e0 = __expf(x0 - m), e1 = __expf(x1 - m);
            float sum = e0 + e1;
            #pragma unroll
            for (int o = 16; o; o >>= 1) sum += __shfl_xor_sync(0xffffffffu, sum, o);
            float inv = 1.0f / sum;
            ss[i * 64 + lane]      = e0 * inv;
            ss[i * 64 + 32 + lane] = e1 * inv;
        }
    }
    __syncthreads();

    for (int t = tid; t < 1024; t += 256)
        reinterpret_cast<float4*>(sq)[t] = reinterpret_cast<const float4*>(vg)[t];
    __syncthreads();

    #pragma unroll
    for (int t = 0; t < 4; t++) {
        int gidx = tid + (t << 8);
        int i  = gidx >> 4;
        int d4 = (gidx & 15) * 4;
        float ox = 0.f, oy = 0.f, oz = 0.f, ow = 0.f;
        #pragma unroll 16
        for (int j = 0; j < 64; j++) {
            float a = ss[i * 64 + j];
            float4 v4 = *reinterpret_cast<const float4*>(&sq[j * 64 + d4]);
            ox += a * v4.x; oy += a * v4.y; oz += a * v4.z; ow += a * v4.w;
        }
        float4 o4; o4.x = ox; o4.y = oy; o4.z = oz; o4.w = ow;
        *reinterpret_cast<float4*>(&g_o[(long long)(b * 64 + i) * PF + h * 64 + d4]) = o4;
    }
}

// ---------------------------------------------------------------------------
extern "C" void kernel_launch(void* const* d_in, const int* in_sizes, int n_in,
                              void* d_out, int out_size) {
    const float* x  = (const float*)d_in[0];
    const float* Wq = (const float*)d_in[1];
    const float* bq = (const float*)d_in[2];
    const float* Wk = (const float*)d_in[3];
    const float* bk = (const float*)d_in[4];
    const float* Wv = (const float*)d_in[5];
    const float* bv = (const float*)d_in[6];
    const float* Wo = (const float*)d_in[7];
    const float* bo = (const float*)d_in[8];
    float* out = (float*)d_out;

    cudaFuncSetAttribute(tc_gemm<0>, cudaFuncAttributeMaxDynamicSharedMemorySize, DSMEM);
    cudaFuncSetAttribute(tc_gemm<1>, cudaFuncAttributeMaxDynamicSharedMemorySize, DSMEM);

    // 1) QKV projection (+bias) into g_qkv, with interleaved tail-copy blocks
    //    576 gemm blocks + 192 copy blocks (every 4th)
    tc_gemm<0><<<768, 256, DSMEM>>>(x, Wq, Wk, Wv, bq, bk, bv, out);

    // 2) attention per (b,h)
    attn_kernel<<<PB * PH, 256>>>();

    // 3) output projection (+bo) into d_out[:, :64, :]: 192 blocks
    tc_gemm<1><<<192, 256, DSMEM>>>(nullptr, Wo, nullptr, nullptr,
                                    bo, nullptr, nullptr, out);
}

// round 11
// speedup vs baseline: 1.2256x; 1.2231x over previous
#include <cuda_runtime.h>
#include <cstdint>

// Problem constants
#define PB   64
#define PS   1024
#define PF   768
#define PH   12
#define PP2  64
#define HEADSZ 4096
#define QKVSTRIDE (PB * PH * HEADSZ)   // 3,145,728

__device__ float g_qkv[3LL * QKVSTRIDE];
__device__ float g_o[4096LL * PF];

// ---------------------------------------------------------------------------
// PTX helpers
// ---------------------------------------------------------------------------
__device__ __forceinline__ void cp16(void* s, const void* g) {
    unsigned sa = (unsigned)__cvta_generic_to_shared(s);
    asm volatile("cp.async.cg.shared.global [%0], [%1], 16;\n" :: "r"(sa), "l"(g));
}
__device__ __forceinline__ void cp_commit() { asm volatile("cp.async.commit_group;\n"); }
template <int N>
__device__ __forceinline__ void cp_wait() { asm volatile("cp.async.wait_group %0;\n" :: "n"(N)); }

__device__ __forceinline__ void mma_tf32(float* c, const unsigned* a, const unsigned* b) {
    asm volatile(
        "mma.sync.aligned.m16n8k8.row.col.f32.tf32.tf32.f32 "
        "{%0,%1,%2,%3}, {%4,%5,%6,%7}, {%8,%9}, {%0,%1,%2,%3};"
        : "+f"(c[0]), "+f"(c[1]), "+f"(c[2]), "+f"(c[3])
        : "r"(a[0]), "r"(a[1]), "r"(a[2]), "r"(a[3]), "r"(b[0]), "r"(b[1]));
}

// Fine-grained streaming tail-copy chunk: x[:,64:,:] -> out[:,64:,:]
#define CCHUNK 12288    // float4 per chunk; 960 chunks total
__device__ __forceinline__ void copy_chunk(int cb, const float4* __restrict__ src,
                                           float4* __restrict__ dst, int tid) {
    const int PERB = (PS - PP2) * (PF / 4);        // 184320
    int base = cb * CCHUNK;
    #pragma unroll 4
    for (int t = tid; t < CCHUNK; t += 256) {
        int i = base + t;
        int b = i / PERB;
        int rem = i - b * PERB;
        long long off = (long long)b * (PS * (PF / 4)) + PP2 * (PF / 4) + rem;
        __stcs(dst + off, __ldcs(src + off));
    }
}

// ---------------------------------------------------------------------------
// TF32 mma.sync GEMM. Block tile 128x128, BK=32, 3-stage cp.async,
// ONE __syncthreads per K-iteration. 8 warps as 2(M) x 4(N), warp tile 64x32.
// MODE 0: C[4096,2304] = Xw @ [Wq;Wk;Wv]^T + bias -> g_qkv[which][b][h][s][d]
//         2D grid (32, 18), pure GEMM.
// MODE 1: C[4096, 768] = O  @ Wo^T         + bo   -> d_out[b][s][c] (s < 64)
//         1D grid: 192 gemm blocks + 480 appended copy chunks.
// ---------------------------------------------------------------------------
#define BK   32
#define LDK  36                         // 32 + 4: 16B-aligned rows, conflict-free frags
#define STAGEF ((128 + 128) * LDK)      // 9216 floats / stage
#define NSTG 3
#define DSMEM  (NSTG * STAGEF * 4)      // 110592 B -> 2 CTAs/SM
#define NKI  (PF / BK)                  // 24

template <int MODE>
__global__ void __launch_bounds__(256, 2) tc_gemm(
    const float* __restrict__ A,
    const float* __restrict__ W0, const float* __restrict__ W1, const float* __restrict__ W2,
    const float* __restrict__ b0, const float* __restrict__ b1, const float* __restrict__ b2,
    float* __restrict__ Cout)
{
    extern __shared__ float sm[];
    const int tid = threadIdx.x;

    int bx, ny;
    if (MODE == 1) {
        int bid = blockIdx.x;
        if (bid >= 192) {
            // appended copy chunks 480..959
            copy_chunk(bid - 192 + 480, (const float4*)A, (float4*)(Cout /*unused*/), tid);
            return;
        }
        bx = bid & 31;
        ny = bid >> 5;
    } else {
        bx = blockIdx.x;
        ny = blockIdx.y;
    }

    const int wid  = tid >> 5;
    const int lane = tid & 31;
    const int wm   = wid >> 2;           // 0..1
    const int wn   = wid & 3;            // 0..3
    const int g    = lane >> 2;          // 0..7
    const int t4   = lane & 3;           // 0..3

    const int m0 = bx * 128;
    const float* W; const float* bias; int nbw; int wsel = 0;
    if (MODE == 0) {
        wsel = ny / 6;
        nbw  = (ny % 6) * 128;
        W    = (wsel == 0) ? W0 : (wsel == 1 ? W1 : W2);
        bias = (wsel == 0) ? b0 : (wsel == 1 ? b1 : b2);
    } else {
        W = W0; bias = b0; nbw = ny * 128;
    }
    const float* Ap = (MODE == 0) ? A : g_o;

    // Stage loader: A 128x32 + B 128x32, 4+4 cp16 per thread
    auto load_stage = [&](int buf, int k0) {
        float* As = sm + buf * STAGEF;
        float* Bs = As + 128 * LDK;
        #pragma unroll
        for (int p = 0; p < 4; p++) {
            int idx = tid + p * 256;
            int r = idx >> 3, c4 = (idx & 7) * 4;
            int gm = m0 + r;
            const float* ga = (MODE == 0)
                ? Ap + ((long long)(gm >> 6) * PS + (gm & 63)) * PF + k0 + c4
                : Ap + (long long)gm * PF + k0 + c4;
            cp16(&As[r * LDK + c4], ga);
        }
        #pragma unroll
        for (int p = 0; p < 4; p++) {
            int idx = tid + p * 256;
            int r = idx >> 3, c4 = (idx & 7) * 4;
            const float* gb = W + (long long)(nbw + r) * PF + k0 + c4;
            cp16(&Bs[r * LDK + c4], gb);
        }
    };

    float acc[4][4][4];
    #pragma unroll
    for (int mi = 0; mi < 4; mi++)
        #pragma unroll
        for (int ni = 0; ni < 4; ni++)
            #pragma unroll
            for (int q = 0; q < 4; q++) acc[mi][ni][q] = 0.0f;

    load_stage(0, 0);
    cp_commit();
    load_stage(1, BK);
    cp_commit();

    int buf = 0;
    for (int i = 0; i < NKI; i++) {
        if (i < NKI - 1) { cp_wait<1>(); } else { cp_wait<0>(); }
        __syncthreads();
        if (i + 2 < NKI) {
            int lb = buf + 2; if (lb >= NSTG) lb -= NSTG;
            load_stage(lb, (i + 2) * BK);
            cp_commit();
        }

        const float* As = sm + buf * STAGEF;
        const float* Bs = As + 128 * LDK;
        const float* ab = As + (wm * 64 + g) * LDK + t4;
        const float* bb = Bs + (wn * 32 + g) * LDK + t4;

        #pragma unroll
        for (int kk = 0; kk < BK; kk += 8) {
            unsigned af[4][4];
            #pragma unroll
            for (int mi = 0; mi < 4; mi++) {
                const float* p = ab + mi * 16 * LDK + kk;
                af[mi][0] = __float_as_uint(p[0]);
                af[mi][1] = __float_as_uint(p[8 * LDK]);
                af[mi][2] = __float_as_uint(p[4]);
                af[mi][3] = __float_as_uint(p[8 * LDK + 4]);
            }
            unsigned bf[4][2];
            #pragma unroll
            for (int ni = 0; ni < 4; ni++) {
                const float* p = bb + ni * 8 * LDK + kk;
                bf[ni][0] = __float_as_uint(p[0]);
                bf[ni][1] = __float_as_uint(p[4]);
            }
            #pragma unroll
            for (int mi = 0; mi < 4; mi++)
                #pragma unroll
                for (int ni = 0; ni < 4; ni++)
                    mma_tf32(acc[mi][ni], af[mi], bf[ni]);
        }

        buf++; if (buf >= NSTG) buf -= NSTG;
    }

    // Bias per ni (float2, col pair this thread owns)
    float2 bfrag[4];
    #pragma unroll
    for (int ni = 0; ni < 4; ni++)
        bfrag[ni] = *reinterpret_cast<const float2*>(bias + nbw + wn * 32 + ni * 8 + t4 * 2);

    // Epilogue: direct global float2 stores from accumulators
    #pragma unroll
    for (int mi = 0; mi < 4; mi++) {
        #pragma unroll
        for (int half = 0; half < 2; half++) {
            int gm = m0 + wm * 64 + mi * 16 + g + half * 8;
            int bb_ = gm >> 6, ss_ = gm & 63;
            #pragma unroll
            for (int ni = 0; ni < 4; ni++) {
                int n = nbw + wn * 32 + ni * 8 + t4 * 2;
                float2 v;
                v.x = acc[mi][ni][half * 2 + 0] + bfrag[ni].x;
                v.y = acc[mi][ni][half * 2 + 1] + bfrag[ni].y;
                if (MODE == 0) {
                    int h = n >> 6, d = n & 63;
                    float* dst = g_qkv + (long long)wsel * QKVSTRIDE
                               + (long long)(bb_ * PH + h) * HEADSZ + ss_ * 64 + d;
                    *reinterpret_cast<float2*>(dst) = v;
                } else {
                    float* dst = Cout + ((long long)bb_ * PS + ss_) * PF + n;
                    *reinterpret_cast<float2*>(dst) = v;
                }
            }
        }
    }
}

// gemm<1> needs x and out for its copy chunks; pass x via A2 param trick:
// we reuse A (first param) as the copy source and Cout as both gemm dst and copy dst.
// A separate wrapper below passes x in a dedicated param.

// ---------------------------------------------------------------------------
// Attention (blocks 0..767) + copy chunks 0..479 (blocks 768..1247).
// ---------------------------------------------------------------------------
__global__ void __launch_bounds__(256) attn_copy_kernel(const float4* __restrict__ x,
                                                        float4* __restrict__ out) {
    __shared__ float sq[64 * 64];
    __shared__ float sk[64 * 64];
    __shared__ float ss[64 * 64];

    const int tid = threadIdx.x;

    if (blockIdx.x >= PB * PH) {
        copy_chunk(blockIdx.x - PB * PH, x, out, tid);
        return;
    }

    const int b = blockIdx.x / PH;
    const int h = blockIdx.x % PH;
    const float* qg = g_qkv + (long long)(b * PH + h) * HEADSZ;
    const float* kg = qg + (long long)QKVSTRIDE;
    const float* vg = kg + (long long)QKVSTRIDE;
    const int lane = tid & 31;

    for (int t = tid; t < 1024; t += 256)
        reinterpret_cast<float4*>(sq)[t] = reinterpret_cast<const float4*>(qg)[t];
    for (int t = tid; t < 1024; t += 256) {
        int j = t >> 4, d4 = (t & 15) * 4;
        float4 v = reinterpret_cast<const float4*>(kg)[t];
        *reinterpret_cast<float4*>(&sk[j * 64 + (d4 ^ ((j & 7) << 3))]) = v;
    }
    __syncthreads();

    #pragma unroll
    for (int t = 0; t < 16; t++) {
        int idx = tid + (t << 8);
        int i = idx >> 6, j = idx & 63;
        int sw = (j & 7) << 3;
        float s = 0.f;
        #pragma unroll
        for (int dd = 0; dd < 64; dd += 4) {
            float4 q4 = *reinterpret_cast<const float4*>(&sq[i * 64 + dd]);
            float4 k4 = *reinterpret_cast<const float4*>(&sk[j * 64 + (dd ^ sw)]);
            s += q4.x * k4.x + q4.y * k4.y + q4.z * k4.z + q4.w * k4.w;
        }
        ss[idx] = s * 0.125f;
    }
    __syncthreads();

    {
        int w = tid >> 5;
        #pragma unroll
        for (int rr = 0; rr < 8; rr++) {
            int i = w * 8 + rr;
            float x0 = ss[i * 64 + lane];
            float x1 = ss[i * 64 + 32 + lane];
            float m = fmaxf(x0, x1);
            #pragma unroll
            for (int o = 16; o; o >>= 1) m = fmaxf(m, __shfl_xor_sync(0xffffffffu, m, o));
            float e0 = __expf(x0 - m), e1 = __expf(x1 - m);
            float sum = e0 + e1;
            #pragma unroll
            for (int o = 16; o; o >>= 1) sum += __shfl_xor_sync(0xffffffffu, sum, o);
            float inv = 1.0f / sum;
            ss[i * 64 + lane]      = e0 * inv;
            ss[i * 64 + 32 + lane] = e1 * inv;
        }
    }
    __syncthreads();

    for (int t = tid; t < 1024; t += 256)
        reinterpret_cast<float4*>(sq)[t] = reinterpret_cast<const float4*>(vg)[t];
    __syncthreads();

    #pragma unroll
    for (int t = 0; t < 4; t++) {
        int gidx = tid + (t << 8);
        int i  = gidx >> 4;
        int d4 = (gidx & 15) * 4;
        float ox = 0.f, oy = 0.f, oz = 0.f, ow = 0.f;
        #pragma unroll 16
        for (int j = 0; j < 64; j++) {
            float a = ss[i * 64 + j];
            float4 v4 = *reinterpret_cast<const float4*>(&sq[j * 64 + d4]);
            ox += a * v4.x; oy += a * v4.y; oz += a * v4.z; ow += a * v4.w;
        }
        float4 o4; o4.x = ox; o4.y = oy; o4.z = oz; o4.w = ow;
        *reinterpret_cast<float4*>(&g_o[(long long)(b * 64 + i) * PF + h * 64 + d4]) = o4;
    }
}

// ---------------------------------------------------------------------------
// gemm<1> variant with copy support: A param carries x (copy source).
// GEMM A-matrix is g_o (hardcoded for MODE 1), so no conflict.
// ---------------------------------------------------------------------------

extern "C" void kernel_launch(void* const* d_in, const int* in_sizes, int n_in,
                              void* d_out, int out_size) {
    const float* x  = (const float*)d_in[0];
    const float* Wq = (const float*)d_in[1];
    const float* bq = (const float*)d_in[2];
    const float* Wk = (const float*)d_in[3];
    const float* bk = (const float*)d_in[4];
    const float* Wv = (const float*)d_in[5];
    const float* bv = (const float*)d_in[6];
    const float* Wo = (const float*)d_in[7];
    const float* bo = (const float*)d_in[8];
    float* out = (float*)d_out;

    cudaFuncSetAttribute(tc_gemm<0>, cudaFuncAttributeMaxDynamicSharedMemorySize, DSMEM);
    cudaFuncSetAttribute(tc_gemm<1>, cudaFuncAttributeMaxDynamicSharedMemorySize, DSMEM);

    // 1) QKV projection (+bias) into g_qkv: pure GEMM, 32 x 18 tiles
    tc_gemm<0><<<dim3(32, 18), 256, DSMEM>>>(x, Wq, Wk, Wv, bq, bk, bv, nullptr);

    // 2) attention per (b,h) + copy chunks [0, 480)
    attn_copy_kernel<<<PB * PH + 480, 256>>>((const float4*)x, (float4*)out);

    // 3) output projection (+bo) into d_out[:, :64, :] + copy chunks [480, 960)
    //    A param carries x as the copy source for appended copy blocks.
    tc_gemm<1><<<192 + 480, 256, DSMEM>>>(x, Wo, nullptr, nullptr,
                                          bo, nullptr, nullptr, out);
}